// round 5
// baseline (speedup 1.0000x reference)
#include <cuda_runtime.h>
#include <cuda_bf16.h>
#include <cstdint>

// SigmaModel: x=[s,a](40) -> relu GEMM1 (64) -> GEMM2 (528 tri) -> symmetric
// 32x32 with exp() diagonal. B = 131072, out fp32 [B,32,32].
//
// R2: software-pipelined producer/consumer.
//  - 608 threads: warps 0..16 = consumers (528 active, one tri output each,
//    W2 row in 32 packed u64 registers for the whole kernel).
//    warps 17..18 = producers (64 threads, one h row each, W1 row in 40 regs).
//  - Double-buffered h: producers compute h for group g+1 (gmem x loads folded
//    straight into FFMA) while consumers compute outputs for group g.
//  - E=8 elements/iteration, 2 barriers/iteration. 131072 % 8 == 0 and each
//    block's slice is contiguous -> no partial groups, no guards.
//  - Store: all 19 warps, 256 coalesced 128B row tasks via dense->tri LUT.

#define BATCH   131072
#define DIM     32
#define ADIM    8
#define INDIM   40
#define HID     64
#define TRI     528
#define NTHR    608
#define E       8

__device__ __forceinline__ unsigned long long pack2(float lo, float hi) {
    unsigned long long p;
    asm("mov.b64 %0, {%1, %2};" : "=l"(p) : "f"(lo), "f"(hi));
    return p;
}
__device__ __forceinline__ void unpack2(unsigned long long p, float& lo, float& hi) {
    asm("mov.b64 {%0, %1}, %2;" : "=f"(lo), "=f"(hi) : "l"(p));
}
__device__ __forceinline__ unsigned long long fma2(unsigned long long a,
                                                   unsigned long long b,
                                                   unsigned long long c) {
    unsigned long long d;
    asm("fma.rn.f32x2 %0, %1, %2, %3;" : "=l"(d) : "l"(a), "l"(b), "l"(c));
    return d;
}

struct __align__(16) HBuf { float h[E][HID]; };

__device__ __forceinline__ void produce_group(long long base,
                                              const float* __restrict__ s,
                                              const float* __restrict__ a,
                                              const float* __restrict__ w1r,
                                              float b1r, int hrow,
                                              HBuf* hb)
{
    #pragma unroll
    for (int e = 0; e < E; ++e) {
        const float4* sp = reinterpret_cast<const float4*>(s + (base + e) * DIM);
        const float4* ap = reinterpret_cast<const float4*>(a + (base + e) * ADIM);
        float acc = b1r;
        #pragma unroll
        for (int q = 0; q < 8; ++q) {
            float4 v = __ldg(sp + q);
            acc = fmaf(w1r[4*q+0], v.x, acc);
            acc = fmaf(w1r[4*q+1], v.y, acc);
            acc = fmaf(w1r[4*q+2], v.z, acc);
            acc = fmaf(w1r[4*q+3], v.w, acc);
        }
        #pragma unroll
        for (int q = 0; q < 2; ++q) {
            float4 v = __ldg(ap + q);
            acc = fmaf(w1r[32+4*q+0], v.x, acc);
            acc = fmaf(w1r[32+4*q+1], v.y, acc);
            acc = fmaf(w1r[32+4*q+2], v.z, acc);
            acc = fmaf(w1r[32+4*q+3], v.w, acc);
        }
        hb->h[e][hrow] = fmaxf(acc, 0.0f);
    }
}

__global__ void __launch_bounds__(NTHR, 1)
sigma_kernel(const float* __restrict__ s,
             const float* __restrict__ a,
             const float* __restrict__ W1,
             const float* __restrict__ b1,
             const float* __restrict__ W2,
             const float* __restrict__ b2,
             float* __restrict__ out)
{
    __shared__ HBuf           h_sm[2];
    __shared__ float          stage[E][TRI];
    __shared__ unsigned short lut[DIM * DIM];

    const int tid  = threadIdx.x;
    const int wid  = tid >> 5;
    const int lane = tid & 31;

    // dense (i,j) -> tri index LUT
    for (int idx = tid; idx < DIM * DIM; idx += NTHR) {
        int i = idx >> 5, j = idx & 31;
        int ii = min(i, j), jj = max(i, j);
        lut[idx] = (unsigned short)(ii * (2 * DIM + 1 - ii) / 2 + (jj - ii));
    }

    const bool is_prod = (tid >= 544);
    const bool is_cons = (tid < TRI);

    // consumer: W2 row in registers
    unsigned long long w2r[32];
    float b2r = 0.0f;
    if (is_cons) {
        const ulonglong2* wrow = reinterpret_cast<const ulonglong2*>(W2 + (size_t)tid * HID);
        #pragma unroll
        for (int q = 0; q < 16; ++q) {
            ulonglong2 v = wrow[q];
            w2r[2*q]   = v.x;
            w2r[2*q+1] = v.y;
        }
        b2r = b2[tid];
    }

    // producer: W1 row in registers
    const int hrow = tid - 544;
    float w1r[INDIM];
    float b1r = 0.0f;
    if (is_prod) {
        #pragma unroll
        for (int k = 0; k < INDIM; ++k) w1r[k] = W1[hrow * INDIM + k];
        b1r = b1[hrow];
    }

    const long long gstride = (long long)gridDim.x * E;
    const long long base0   = (long long)blockIdx.x * E;

    // prologue: fill buffer 0 for the first group
    if (is_prod && base0 < BATCH)
        produce_group(base0, s, a, w1r, b1r, hrow, &h_sm[0]);
    __syncthreads();

    int buf = 0;
    for (long long base = base0; base < BATCH; base += gstride) {
        const long long nbase = base + gstride;

        if (is_prod) {
            if (nbase < BATCH)
                produce_group(nbase, s, a, w1r, b1r, hrow, &h_sm[buf ^ 1]);
        } else if (is_cons) {
            const ulonglong2* hq = reinterpret_cast<const ulonglong2*>(&h_sm[buf]);
            // 16 ulonglong2 per element row
            #pragma unroll
            for (int eo = 0; eo < E; eo += 2) {
                unsigned long long acc0 = pack2(b2r, 0.0f);
                unsigned long long acc1 = pack2(b2r, 0.0f);
                const ulonglong2* h0 = hq + (eo    ) * 16;
                const ulonglong2* h1 = hq + (eo + 1) * 16;
                #pragma unroll
                for (int q = 0; q < 16; ++q) {
                    ulonglong2 a0 = h0[q];
                    ulonglong2 a1 = h1[q];
                    acc0 = fma2(w2r[2*q],   a0.x, acc0);
                    acc0 = fma2(w2r[2*q+1], a0.y, acc0);
                    acc1 = fma2(w2r[2*q],   a1.x, acc1);
                    acc1 = fma2(w2r[2*q+1], a1.y, acc1);
                }
                float lo, hi;
                unpack2(acc0, lo, hi);
                stage[eo][tid] = lo + hi;
                unpack2(acc1, lo, hi);
                stage[eo + 1][tid] = lo + hi;
            }
        }
        __syncthreads();

        // store: 256 row tasks over all 19 warps
        for (int task = wid; task < E * DIM; task += NTHR / 32) {
            int e = task >> 5;
            int i = task & 31;
            int t = lut[(i << 5) | lane];
            float v = stage[e][t];
            if (lane == i) v = __expf(v);
            out[(base + e) * (DIM * DIM) + (i << 5) + lane] = v;
        }
        __syncthreads();

        buf ^= 1;
    }
}

extern "C" void kernel_launch(void* const* d_in, const int* in_sizes, int n_in,
                              void* d_out, int out_size)
{
    const float* s  = (const float*)d_in[0];
    const float* a  = (const float*)d_in[1];
    const float* W1 = (const float*)d_in[2];
    const float* b1 = (const float*)d_in[3];
    const float* W2 = (const float*)d_in[4];
    const float* b2 = (const float*)d_in[5];
    float* out = (float*)d_out;

    int nsm = 148;
    cudaDeviceGetAttribute(&nsm, cudaDevAttrMultiProcessorCount, 0);

    sigma_kernel<<<nsm, NTHR>>>(s, a, W1, b1, W2, b2, out);
}

// round 8
// speedup vs baseline: 3.5758x; 3.5758x over previous
#include <cuda_runtime.h>
#include <cuda_bf16.h>
#include <cstdint>

// SigmaModel: x(40) -> relu GEMM1(64) [FFMA] -> GEMM2 (528 of padded 544)
// [mma.sync m16n8k16 bf16, 3-term hi/lo split precision, fp32 accum]
// -> symmetric 32x32 with exp diag.  B=131072, out fp32 [B,32,32].
//
// tcgen05 is unavailable (harness PTX target is sm_103, not sm_103a), so the
// tensor path uses portable ldmatrix + mma.sync (sm_80+).
//
// Per 32-element tile: 8 warps = 2 m-blocks x 4 n-quarters (17 n8-tiles each,
// acc[17][4] fp32 in regs). W2 hi/lo persistent in SW128 smem; A hi/lo written
// by the FFMA layer-1. Epilogue: acc + b2 -> stage smem -> tri LUT gather ->
// coalesced row stores.

#define BATCH  131072
#define DIM    32
#define ADIM   8
#define INDIM  40
#define HID    64
#define TRI    528
#define TRIP   544
#define NTHR   256
#define TM     32
#define NTILES (BATCH / TM)
#define SSTR   530   // stage row stride (floats), even for float2, odd/2-banked

// smem byte offsets
#define OFF_BHI   0        // W2 hi bf16, SW128 atoms, 544 rows -> 69632 B
#define OFF_BLO   69632
#define OFF_AHI   139264   // A hi bf16 [32][64] SW128 -> 4096 B
#define OFF_ALO   143360
#define OFF_STAGE 147456   // f32 [32][SSTR] = 67840 B
#define OFF_W1    215296   // f32 [64][41]
#define OFF_B2    225792   // f32 [544]
#define OFF_B1    227968   // f32 [64]
#define OFF_LUT   228224   // u16 [1024]
#define SMEM_BYTES 230272

#define SW128(x) ((x) ^ (((x) >> 3) & 0x70))

__device__ __forceinline__ uint32_t smem_u32(const void* p) {
    uint32_t r;
    asm("{ .reg .u64 t; cvta.to.shared.u64 t, %1; cvt.u32.u64 %0, t; }" : "=r"(r) : "l"(p));
    return r;
}
__device__ __forceinline__ void ldsm_x4(uint32_t& r0, uint32_t& r1, uint32_t& r2,
                                        uint32_t& r3, uint32_t addr) {
    asm volatile("ldmatrix.sync.aligned.m8n8.x4.shared.b16 {%0,%1,%2,%3}, [%4];"
                 : "=r"(r0), "=r"(r1), "=r"(r2), "=r"(r3) : "r"(addr));
}
__device__ __forceinline__ void ldsm_x2(uint32_t& r0, uint32_t& r1, uint32_t addr) {
    asm volatile("ldmatrix.sync.aligned.m8n8.x2.shared.b16 {%0,%1}, [%2];"
                 : "=r"(r0), "=r"(r1) : "r"(addr));
}
__device__ __forceinline__ void mma_bf16(float* d, const uint32_t* a,
                                         uint32_t b0, uint32_t b1) {
    asm("mma.sync.aligned.m16n8k16.row.col.f32.bf16.bf16.f32 "
        "{%0,%1,%2,%3},{%4,%5,%6,%7},{%8,%9},{%0,%1,%2,%3};"
        : "+f"(d[0]), "+f"(d[1]), "+f"(d[2]), "+f"(d[3])
        : "r"(a[0]), "r"(a[1]), "r"(a[2]), "r"(a[3]), "r"(b0), "r"(b1));
}

__global__ void __launch_bounds__(NTHR, 1)
sigma_kernel(const float* __restrict__ s,
             const float* __restrict__ a,
             const float* __restrict__ W1,
             const float* __restrict__ b1,
             const float* __restrict__ W2,
             const float* __restrict__ b2,
             float* __restrict__ out)
{
    extern __shared__ char sm[];
    const uint32_t smb = smem_u32(sm);

    float*          w1s    = (float*)(sm + OFF_W1);
    float*          b2s    = (float*)(sm + OFF_B2);
    float*          b1s    = (float*)(sm + OFF_B1);
    unsigned short* lut    = (unsigned short*)(sm + OFF_LUT);
    float*          stagef = (float*)(sm + OFF_STAGE);

    const int tid  = threadIdx.x;
    const int wid  = tid >> 5;
    const int lane = tid & 31;

    // ---------------- one-time setup ----------------
    // W2 -> bf16 hi/lo, SW128 blocked atoms (8 rows x 128B). rows>=528 zero.
    for (int idx = tid; idx < TRIP * HID; idx += NTHR) {
        int r = idx >> 6, k = idx & 63;
        float w = (r < TRI) ? W2[r * HID + k] : 0.0f;
        __nv_bfloat16 hi = __float2bfloat16(w);
        __nv_bfloat16 lo = __float2bfloat16(w - __bfloat162float(hi));
        uint32_t off = ((r >> 3) << 10) + SW128(((r & 7) << 7) + (k << 1));
        *(__nv_bfloat16*)(sm + OFF_BHI + off) = hi;
        *(__nv_bfloat16*)(sm + OFF_BLO + off) = lo;
    }
    for (int idx = tid; idx < HID * INDIM; idx += NTHR)
        w1s[(idx / INDIM) * 41 + (idx % INDIM)] = W1[idx];
    for (int t = tid; t < TRIP; t += NTHR) b2s[t] = (t < TRI) ? b2[t] : 0.0f;
    if (tid < HID) b1s[tid] = b1[tid];
    for (int idx = tid; idx < DIM * DIM; idx += NTHR) {
        int i = idx >> 5, j = idx & 31;
        int ii = min(i, j), jj = max(i, j);
        lut[idx] = (unsigned short)(ii * (2 * DIM + 1 - ii) / 2 + (jj - ii));
    }
    __syncthreads();

    // layer-1 mapping: thread -> (h row, 8-element group)
    const int r_h = tid & 63;
    const int eg0 = (tid >> 6) << 3;

    // MMA mapping: warp -> (m-block, n-quarter)
    const int mb = wid >> 2;       // 0..1 (16 elements each)
    const int ns = wid & 3;        // 0..3 (136 outputs each)
    const int eb = mb << 4;

    // ldmatrix lane address components (constant across tiles)
    const uint32_t arow   = eb + (lane & 15);
    const uint32_t a_atom = (arow >> 3) << 10;
    const uint32_t a_row7 = (arow & 7) << 7;
    const uint32_t a_kadd = (lane >> 4) << 4;       // +16B for k8..15 matrices
    const uint32_t b_row7 = (lane & 7) << 7;
    const uint32_t b_kadd = ((lane >> 3) & 1) << 4; // +16B for b1 matrix
    const uint32_t b_atom0 = (ns * 136) >> 3;       // t_base/8, + nt per tile

    for (int tile = blockIdx.x; tile < NTILES; tile += gridDim.x) {
        // ---------- layer 1: h = relu(W1 x + b1) -> A hi/lo (bf16, SW128) ----------
        {
            float w1r[INDIM];
            #pragma unroll
            for (int k = 0; k < INDIM; ++k) w1r[k] = w1s[r_h * 41 + k];
            const float b1r = b1s[r_h];
            #pragma unroll 2
            for (int eo = 0; eo < 8; ++eo) {
                int e = eg0 + eo;
                long long ge = (long long)tile * TM + e;
                const float4* sp = (const float4*)(s + ge * DIM);
                const float4* ap = (const float4*)(a + ge * ADIM);
                float acc = b1r;
                #pragma unroll
                for (int q = 0; q < 8; ++q) {
                    float4 v = __ldg(sp + q);
                    acc = fmaf(w1r[4*q+0], v.x, acc);
                    acc = fmaf(w1r[4*q+1], v.y, acc);
                    acc = fmaf(w1r[4*q+2], v.z, acc);
                    acc = fmaf(w1r[4*q+3], v.w, acc);
                }
                #pragma unroll
                for (int q = 0; q < 2; ++q) {
                    float4 v = __ldg(ap + q);
                    acc = fmaf(w1r[32+4*q+0], v.x, acc);
                    acc = fmaf(w1r[32+4*q+1], v.y, acc);
                    acc = fmaf(w1r[32+4*q+2], v.z, acc);
                    acc = fmaf(w1r[32+4*q+3], v.w, acc);
                }
                float h = fmaxf(acc, 0.0f);
                __nv_bfloat16 hi = __float2bfloat16(h);
                __nv_bfloat16 lo = __float2bfloat16(h - __bfloat162float(hi));
                uint32_t off = ((e >> 3) << 10) + SW128(((e & 7) << 7) + (r_h << 1));
                *(__nv_bfloat16*)(sm + OFF_AHI + off) = hi;
                *(__nv_bfloat16*)(sm + OFF_ALO + off) = lo;
            }
        }
        __syncthreads();

        // ---------- GEMM2: mma.sync, 3-term split, acc[17][4] ----------
        float acc[17][4];
        #pragma unroll
        for (int nt = 0; nt < 17; ++nt)
            acc[nt][0] = acc[nt][1] = acc[nt][2] = acc[nt][3] = 0.0f;

        #pragma unroll
        for (int kc = 0; kc < 4; ++kc) {
            uint32_t a_off = a_atom + SW128(a_row7 + kc * 32 + a_kadd);
            uint32_t ahi[4], alo[4];
            ldsm_x4(ahi[0], ahi[1], ahi[2], ahi[3], smb + OFF_AHI + a_off);
            ldsm_x4(alo[0], alo[1], alo[2], alo[3], smb + OFF_ALO + a_off);
            uint32_t b_sw = SW128(b_row7 + kc * 32 + b_kadd);
            #pragma unroll
            for (int nt = 0; nt < 17; ++nt) {
                uint32_t b_off = ((b_atom0 + nt) << 10) + b_sw;
                uint32_t bh0, bh1, bl0, bl1;
                ldsm_x2(bh0, bh1, smb + OFF_BHI + b_off);
                ldsm_x2(bl0, bl1, smb + OFF_BLO + b_off);
                mma_bf16(acc[nt], ahi, bh0, bh1);
                mma_bf16(acc[nt], ahi, bl0, bl1);
                mma_bf16(acc[nt], alo, bh0, bh1);
            }
        }

        // ---------- stage: acc + b2 -> stage[e][t] ----------
        {
            int er = eb + (lane >> 2);
            int tc = ns * 136 + ((lane & 3) << 1);
            #pragma unroll
            for (int nt = 0; nt < 17; ++nt) {
                int t0 = tc + nt * 8;
                if (t0 < TRI) {
                    float2 bb = *(const float2*)(b2s + t0);
                    *(float2*)(stagef + er * SSTR + t0) =
                        make_float2(acc[nt][0] + bb.x, acc[nt][1] + bb.y);
                    *(float2*)(stagef + (er + 8) * SSTR + t0) =
                        make_float2(acc[nt][2] + bb.x, acc[nt][3] + bb.y);
                }
            }
        }
        __syncthreads();

        // ---------- store: dense rows via LUT, exp diag, coalesced ----------
        {
            long long base_e = (long long)tile * TM;
            #pragma unroll 4
            for (int it = 0; it < 128; ++it) {
                int task = wid * 128 + it;
                int e = task >> 5, i = task & 31;
                float v = stagef[e * SSTR + lut[(i << 5) | lane]];
                if (lane == i) v = __expf(v);
                out[(base_e + e) * (DIM * DIM) + (i << 5) + lane] = v;
            }
        }
        __syncthreads();
    }
}

extern "C" void kernel_launch(void* const* d_in, const int* in_sizes, int n_in,
                              void* d_out, int out_size)
{
    const float* s  = (const float*)d_in[0];
    const float* a  = (const float*)d_in[1];
    const float* W1 = (const float*)d_in[2];
    const float* b1 = (const float*)d_in[3];
    const float* W2 = (const float*)d_in[4];
    const float* b2 = (const float*)d_in[5];
    float* out = (float*)d_out;

    int nsm = 148;
    cudaDeviceGetAttribute(&nsm, cudaDevAttrMultiProcessorCount, 0);

    cudaFuncSetAttribute(sigma_kernel,
                         cudaFuncAttributeMaxDynamicSharedMemorySize, SMEM_BYTES);
    sigma_kernel<<<nsm, NTHR, SMEM_BYTES>>>(s, a, W1, b1, W2, b2, out);
}

// round 10
// speedup vs baseline: 5.7325x; 1.6032x over previous
#include <cuda_runtime.h>
#include <cuda_bf16.h>
#include <cstdint>

// SigmaModel: x(40) -> relu GEMM1(64) -> GEMM2(528 of padded 544) -> symmetric
// 32x32 with exp diag.  B=131072, out fp32 [B,32,32].
// Both GEMMs on mma.sync m16n8k16 bf16 with 3-term hi/lo split precision.
// Per 32-elem tile: 8 warps = 2 m-blocks x 4 n-quarters.
//  - x staged coalesced -> bf16 hi/lo SW128 smem (once per tile, K padded to 48)
//  - GEMM1 -> h relu'd/split in registers -> bf16 hi/lo A2 smem
//  - GEMM2: W2 hi/lo persistent smem; combined hi/lo ldmatrix.x4 (lane-split
//    addressing); acc[17][4] fp32
//  - stage: acc + b2 -> fp32 smem, diag exp applied via precomputed bitmask
//  - store: per-warp loop-invariant LUT offsets, 4 LDS + STG.128 per element

#define BATCH  131072
#define DIM    32
#define ADIM   8
#define INDIM  40
#define HID    64
#define TRI    528
#define TRIP   544
#define NTHR   256
#define TM     32
#define NTILES (BATCH / TM)
#define SSTR   528

#define OFF_BHI   0          // W2 hi bf16 SW128, 68 atoms (69632 B)
#define OFF_BLO   69632
#define OFF_W1HI  139264     // W1 hi bf16 SW128 [64][64] (8192 B)
#define OFF_W1LO  147456
#define OFF_U     155648     // union: X/A bf16 tiles  |  stage f32 [32][528]
#define OFF_XHI   (OFF_U)
#define OFF_XLO   (OFF_U + 4096)
#define OFF_AHI   (OFF_U + 8192)
#define OFF_ALO   (OFF_U + 12288)
#define OFF_STAGE (OFF_U)
#define OFF_B2    223232     // 544 f32
#define OFF_LUT   225408     // 1024 u16 (stage byte offsets t*4)
#define SMEM_BYTES 227456

#define SW128(x) ((x) ^ (((x) >> 3) & 0x70))

__device__ __forceinline__ uint32_t smem_u32(const void* p) {
    uint32_t r;
    asm("{ .reg .u64 t; cvta.to.shared.u64 t, %1; cvt.u32.u64 %0, t; }" : "=r"(r) : "l"(p));
    return r;
}
__device__ __forceinline__ void ldsm_x4(uint32_t& r0, uint32_t& r1, uint32_t& r2,
                                        uint32_t& r3, uint32_t addr) {
    asm volatile("ldmatrix.sync.aligned.m8n8.x4.shared.b16 {%0,%1,%2,%3}, [%4];"
                 : "=r"(r0), "=r"(r1), "=r"(r2), "=r"(r3) : "r"(addr));
}
__device__ __forceinline__ void mma_bf16(float* d, const uint32_t* a,
                                         uint32_t b0, uint32_t b1) {
    asm("mma.sync.aligned.m16n8k16.row.col.f32.bf16.bf16.f32 "
        "{%0,%1,%2,%3},{%4,%5,%6,%7},{%8,%9},{%0,%1,%2,%3};"
        : "+f"(d[0]), "+f"(d[1]), "+f"(d[2]), "+f"(d[3])
        : "r"(a[0]), "r"(a[1]), "r"(a[2]), "r"(a[3]), "r"(b0), "r"(b1));
}
// pack (lo_v -> low half, hi_v -> high half) as bf16x2 hi; residual as lo.
__device__ __forceinline__ void split2(float lo_v, float hi_v,
                                       uint32_t& hi, uint32_t& lo) {
    asm("cvt.rn.bf16x2.f32 %0, %1, %2;" : "=r"(hi) : "f"(hi_v), "f"(lo_v));
    float f0 = __uint_as_float(hi << 16);
    float f1 = __uint_as_float(hi & 0xFFFF0000u);
    float r0 = lo_v - f0, r1 = hi_v - f1;
    asm("cvt.rn.bf16x2.f32 %0, %1, %2;" : "=r"(lo) : "f"(r1), "f"(r0));
}

__global__ void __launch_bounds__(NTHR, 1)
sigma_kernel(const float* __restrict__ s,
             const float* __restrict__ a,
             const float* __restrict__ W1,
             const float* __restrict__ b1,
             const float* __restrict__ W2,
             const float* __restrict__ b2,
             float* __restrict__ out)
{
    extern __shared__ char sm[];
    const uint32_t smb = smem_u32(sm);

    const int tid  = threadIdx.x;
    const int wid  = tid >> 5;
    const int lane = tid & 31;

    // ---------------- one-time setup ----------------
    for (int idx = tid; idx < TRIP * HID; idx += NTHR) {           // W2 hi/lo
        int r = idx >> 6, k = idx & 63;
        float w = (r < TRI) ? W2[r * HID + k] : 0.0f;
        uint32_t hi, lo; split2(w, 0.0f, hi, lo);
        uint32_t off = ((r >> 3) << 10) + SW128(((r & 7) << 7) + (k << 1));
        *(uint16_t*)(sm + OFF_BHI + off) = (uint16_t)(hi & 0xFFFF);
        *(uint16_t*)(sm + OFF_BLO + off) = (uint16_t)(lo & 0xFFFF);
    }
    for (int idx = tid; idx < 64 * 64; idx += NTHR) {              // W1 hi/lo (pad k>=40)
        int r = idx >> 6, k = idx & 63;
        float w = (k < INDIM) ? W1[r * INDIM + k] : 0.0f;
        uint32_t hi, lo; split2(w, 0.0f, hi, lo);
        uint32_t off = ((r >> 3) << 10) + SW128(((r & 7) << 7) + (k << 1));
        *(uint16_t*)(sm + OFF_W1HI + off) = (uint16_t)(hi & 0xFFFF);
        *(uint16_t*)(sm + OFF_W1LO + off) = (uint16_t)(lo & 0xFFFF);
    }
    for (int t = tid; t < TRIP; t += NTHR)
        ((float*)(sm + OFF_B2))[t] = (t < TRI) ? b2[t] : 0.0f;
    for (int idx = tid; idx < DIM * DIM; idx += NTHR) {            // LUT: byte offsets
        int i = idx >> 5, j = idx & 31;
        int ii = min(i, j), jj = max(i, j);
        int t = ii * (2 * DIM + 1 - ii) / 2 + (jj - ii);
        ((uint16_t*)(sm + OFF_LUT))[idx] = (uint16_t)(t * 4);
    }

    // ---------------- per-lane constants ----------------
    const int mb = wid >> 2, ns = wid & 3;
    const int arow = (mb << 4) + (lane & 15);
    uint32_t aoff[4], w1sw[3], b2sw[4];
    {
        const uint32_t kadd = ((lane >> 3) & 1) << 4;
        const uint32_t losel_w1 = (lane >= 16) ? 8192u : 0u;
        const uint32_t losel_b  = (lane >= 16) ? 69632u : 0u;
        #pragma unroll
        for (int kc = 0; kc < 4; ++kc) {
            aoff[kc] = ((arow >> 3) << 10) +
                       SW128(((arow & 7) << 7) + kc * 32 + ((lane >> 4) << 4));
            uint32_t bs = SW128(((lane & 7) << 7) + kc * 32 + kadd);
            b2sw[kc] = losel_b + bs;
            if (kc < 3) w1sw[kc] = losel_w1 + bs;
        }
    }
    float b1r[4];
    {
        int c_lo = (ns << 4) + ((lane & 3) << 1);
        b1r[0] = b1[c_lo];     b1r[1] = b1[c_lo + 1];
        b1r[2] = b1[c_lo + 8]; b1r[3] = b1[c_lo + 9];
    }
    const int tb = ns * 136 + ((lane & 3) << 1);   // stage col base
    unsigned long long dmask = 0ull;               // diag bits for (t0, t0+1) per nt
    #pragma unroll 1
    for (int nt = 0; nt < 17; ++nt) {
        int t0 = tb + (nt << 3);
        for (int i = 0; i < 32; ++i) {
            int di = i * (65 - i) / 2;
            if (di == t0)     dmask |= 1ull << (2 * nt);
            if (di == t0 + 1) dmask |= 1ull << (2 * nt + 1);
        }
    }
    __syncthreads();

    // store-loop invariants (LUT written above)
    const int srow = (wid << 2) + (lane >> 3);     // dense row i (const per lane)
    const int c0   = (lane & 7) << 2;              // dense col quad
    uint32_t toff[4];
    #pragma unroll
    for (int j = 0; j < 4; ++j)
        toff[j] = ((const uint16_t*)(sm + OFF_LUT))[(srow << 5) + c0 + j];
    const int lane_out = srow * DIM + c0;

    // ---------------- main loop ----------------
    for (int tile = blockIdx.x; tile < NTILES; tile += gridDim.x) {
        const long long ebase = (long long)tile * TM;

        // ---- x-stage: [s|a] -> bf16 hi/lo SW128 (cols 0..39; 40..47 zeroed) ----
        {
            #pragma unroll
            for (int r = 0; r < 2; ++r) {
                int item = tid + (r << 8);
                int e, kp; float2 f;
                if (item < 512) {
                    e = item >> 4; kp = item & 15;
                    f = __ldg((const float2*)(s + (ebase + e) * DIM) + kp);
                } else {
                    int j = item - 512; e = j >> 2; kp = 16 + (j & 3);
                    f = __ldg((const float2*)(a + (ebase + e) * ADIM) + (j & 3));
                }
                uint32_t hi, lo; split2(f.x, f.y, hi, lo);
                uint32_t off = ((e >> 3) << 10) + SW128(((e & 7) << 7) + (kp << 2));
                *(uint32_t*)(sm + OFF_XHI + off) = hi;
                *(uint32_t*)(sm + OFF_XLO + off) = lo;
            }
            if (tid < 128) {
                int j = tid; int e = (j + 512 - 512) >> 2;  // items 512..639
                e = j >> 2; int kp = 16 + (j & 3);
                float2 f = __ldg((const float2*)(a + (ebase + e) * ADIM) + (j & 3));
                // overlap-safe: recompute for correct slice (items 512..639)
                (void)f;
                // NOTE: handled below properly
            }
            // a-part (items 512..639) done by tid<128 in round "r2":
            if (tid < 128) {
                int j = tid; int e = j >> 2; int kp = 16 + (j & 3);
                float2 f = __ldg((const float2*)(a + (ebase + e) * ADIM) + (j & 3));
                uint32_t hi, lo; split2(f.x, f.y, hi, lo);
                uint32_t off = ((e >> 3) << 10) + SW128(((e & 7) << 7) + (kp << 2));
                *(uint32_t*)(sm + OFF_XHI + off) = hi;
                *(uint32_t*)(sm + OFF_XLO + off) = lo;
            }
            // zero pad cols 40..47 (kp 20..23), hi and lo
            {
                int e = tid >> 3, w8 = tid & 7;
                int kp = 20 + (w8 & 3);
                uint32_t off = ((e >> 3) << 10) + SW128(((e & 7) << 7) + (kp << 2));
                *(uint32_t*)(sm + ((w8 >> 2) ? OFF_XLO : OFF_XHI) + off) = 0u;
            }
        }
        __syncthreads();

        // ---- GEMM1: h = relu(x @ W1^T + b1) -> A2 hi/lo ----
        {
            float acc1[2][4];
            #pragma unroll
            for (int n = 0; n < 2; ++n)
                acc1[n][0] = acc1[n][1] = acc1[n][2] = acc1[n][3] = 0.0f;
            #pragma unroll
            for (int kc = 0; kc < 3; ++kc) {
                uint32_t xhi[4], xlo[4];
                ldsm_x4(xhi[0], xhi[1], xhi[2], xhi[3], smb + OFF_XHI + aoff[kc]);
                ldsm_x4(xlo[0], xlo[1], xlo[2], xlo[3], smb + OFF_XLO + aoff[kc]);
                #pragma unroll
                for (int ntl = 0; ntl < 2; ++ntl) {
                    int ntg = (ns << 1) + ntl;
                    uint32_t wh0, wh1, wl0, wl1;
                    ldsm_x4(wh0, wh1, wl0, wl1,
                            smb + OFF_W1HI + (ntg << 10) + w1sw[kc]);
                    mma_bf16(acc1[ntl], xhi, wh0, wh1);
                    mma_bf16(acc1[ntl], xhi, wl0, wl1);
                    mma_bf16(acc1[ntl], xlo, wh0, wh1);
                }
            }
            int r0 = (mb << 4) + (lane >> 2);
            int r1 = r0 + 8;
            #pragma unroll
            for (int ntl = 0; ntl < 2; ++ntl) {
                int c = (ns << 4) + (ntl << 3) + ((lane & 3) << 1);
                float v00 = fmaxf(acc1[ntl][0] + b1r[ntl * 2],     0.0f);
                float v01 = fmaxf(acc1[ntl][1] + b1r[ntl * 2 + 1], 0.0f);
                float v10 = fmaxf(acc1[ntl][2] + b1r[ntl * 2],     0.0f);
                float v11 = fmaxf(acc1[ntl][3] + b1r[ntl * 2 + 1], 0.0f);
                uint32_t hi, lo;
                split2(v00, v01, hi, lo);
                uint32_t off = ((r0 >> 3) << 10) + SW128(((r0 & 7) << 7) + (c << 1));
                *(uint32_t*)(sm + OFF_AHI + off) = hi;
                *(uint32_t*)(sm + OFF_ALO + off) = lo;
                split2(v10, v11, hi, lo);
                off = ((r1 >> 3) << 10) + SW128(((r1 & 7) << 7) + (c << 1));
                *(uint32_t*)(sm + OFF_AHI + off) = hi;
                *(uint32_t*)(sm + OFF_ALO + off) = lo;
            }
        }
        __syncthreads();

        // ---- GEMM2: acc[17][4] = h @ W2^T (3-term split) ----
        float acc[17][4];
        #pragma unroll
        for (int nt = 0; nt < 17; ++nt)
            acc[nt][0] = acc[nt][1] = acc[nt][2] = acc[nt][3] = 0.0f;
        #pragma unroll
        for (int kc = 0; kc < 4; ++kc) {
            uint32_t ahi[4], alo[4];
            ldsm_x4(ahi[0], ahi[1], ahi[2], ahi[3], smb + OFF_AHI + aoff[kc]);
            ldsm_x4(alo[0], alo[1], alo[2], alo[3], smb + OFF_ALO + aoff[kc]);
            uint32_t baddr = smb + OFF_BHI + ((uint32_t)(ns * 17) << 10) + b2sw[kc];
            #pragma unroll
            for (int nt = 0; nt < 17; ++nt) {
                uint32_t bh0, bh1, bl0, bl1;
                ldsm_x4(bh0, bh1, bl0, bl1, baddr);
                baddr += 1024;
                mma_bf16(acc[nt], ahi, bh0, bh1);
                mma_bf16(acc[nt], ahi, bl0, bl1);
                mma_bf16(acc[nt], alo, bh0, bh1);
            }
        }
        __syncthreads();   // A2/X dead before stage overwrites the union

        // ---- stage: acc + b2 -> fp32 smem, exp on diagonal t's ----
        {
            int er = (mb << 4) + (lane >> 2);
            const float* b2s = (const float*)(sm + OFF_B2);
            float* stg = (float*)(sm + OFF_STAGE);
            #pragma unroll
            for (int nt = 0; nt < 17; ++nt) {
                int t0 = tb + (nt << 3);
                if (t0 < TRI) {
                    float2 bb = *(const float2*)(b2s + t0);
                    float v0 = acc[nt][0] + bb.x, v1 = acc[nt][1] + bb.y;
                    float v2 = acc[nt][2] + bb.x, v3 = acc[nt][3] + bb.y;
                    if ((dmask >> (2 * nt)) & 1ull) { v0 = __expf(v0); v2 = __expf(v2); }
                    if ((dmask >> (2 * nt + 1)) & 1ull) { v1 = __expf(v1); v3 = __expf(v3); }
                    *(float2*)(stg + er * SSTR + t0)       = make_float2(v0, v1);
                    *(float2*)(stg + (er + 8) * SSTR + t0) = make_float2(v2, v3);
                }
            }
        }
        __syncthreads();

        // ---- store: loop-invariant gather offsets, STG.128 coalesced ----
        {
            const char* sbase = sm + OFF_STAGE;
            float* ob = out + ebase * (DIM * DIM) + lane_out;
            #pragma unroll 4
            for (int e = 0; e < TM; ++e) {
                const char* srw = sbase + e * (SSTR * 4);
                float v0 = *(const float*)(srw + toff[0]);
                float v1 = *(const float*)(srw + toff[1]);
                float v2 = *(const float*)(srw + toff[2]);
                float v3 = *(const float*)(srw + toff[3]);
                __stcs((float4*)(ob + e * (DIM * DIM)), make_float4(v0, v1, v2, v3));
            }
        }
        __syncthreads();
    }
}

extern "C" void kernel_launch(void* const* d_in, const int* in_sizes, int n_in,
                              void* d_out, int out_size)
{
    const float* s  = (const float*)d_in[0];
    const float* a  = (const float*)d_in[1];
    const float* W1 = (const float*)d_in[2];
    const float* b1 = (const float*)d_in[3];
    const float* W2 = (const float*)d_in[4];
    const float* b2 = (const float*)d_in[5];
    float* out = (float*)d_out;

    int nsm = 148;
    cudaDeviceGetAttribute(&nsm, cudaDevAttrMultiProcessorCount, 0);

    cudaFuncSetAttribute(sigma_kernel,
                         cudaFuncAttributeMaxDynamicSharedMemorySize, SMEM_BYTES);
    sigma_kernel<<<nsm, NTHR, SMEM_BYTES>>>(s, a, W1, b1, W2, b2, out);
}